// round 2
// baseline (speedup 1.0000x reference)
#include <cuda_runtime.h>

#define NUM_CLASSES 23
#define BATCH 8
#define HW (512*512)               // 262144 = 2^18
#define HW_SHIFT 18
#define NPIX (BATCH*HW)            // 2097152
#define GRID 592
#define BLOCK 256
#define NWARPS (BLOCK/32)
#define NVALS (2*NUM_CLASSES + 1)  // 23 inter + 23 denom + 1 ce = 47
#define SMOOTH 1e-5f

// Per-block partials; fully overwritten by every launch (no init needed).
__device__ float g_scratch[NVALS * GRID];

__device__ __forceinline__ float warp_sum(float v) {
    #pragma unroll
    for (int off = 16; off; off >>= 1)
        v += __shfl_down_sync(0xffffffffu, v, off);
    return v;
}

__global__ __launch_bounds__(BLOCK, 2)
void combined_loss_pass1(const float* __restrict__ pred,
                         const int* __restrict__ tgt)
{
    // Register-resident per-class accumulators (compile-time indexed only).
    float acc_int[NUM_CLASSES];
    float acc_den[NUM_CLASSES];
    #pragma unroll
    for (int c = 0; c < NUM_CLASSES; c++) { acc_int[c] = 0.f; acc_den[c] = 0.f; }
    float acc_ce = 0.f;

    const int tid0   = blockIdx.x * BLOCK + threadIdx.x;
    const int stride = GRID * BLOCK;

    for (int p = tid0; p < NPIX; p += stride) {
        const int b  = p >> HW_SHIFT;
        const int hw = p & (HW - 1);
        const float* base = pred + (size_t)b * (NUM_CLASSES * HW) + hw;
        const int t = tgt[p];

        // Pass A: load all class logits (coalesced per class), track max & x_t
        float x[NUM_CLASSES];
        float m  = -1e30f;
        float xt = 0.f;
        #pragma unroll
        for (int c = 0; c < NUM_CLASSES; c++) {
            x[c] = base[c * HW];
            m = fmaxf(m, x[c]);
            xt = (c == t) ? x[c] : xt;
        }

        // Pass B: exp + sum
        float s = 0.f;
        #pragma unroll
        for (int c = 0; c < NUM_CLASSES; c++) {
            x[c] = __expf(x[c] - m);
            s += x[c];
        }
        const float inv = 1.0f / s;

        // Pass C: accumulate per-class dice stats (scatter as predicated add)
        #pragma unroll
        for (int c = 0; c < NUM_CLASSES; c++) {
            const float pr  = x[c] * inv;
            const bool  hit = (c == t);
            acc_den[c] += hit ? (pr + 1.0f) : pr;   // sum_p[c] + counts[c]
            acc_int[c] += hit ? pr : 0.0f;          // inter[c]
        }

        // CE: -(logp_t) = (m + log(sumexp)) - x_t
        acc_ce += (m + __logf(s)) - xt;
    }

    // Deterministic block reduction: warp shfl -> shared -> serial over warps.
    __shared__ float s_part[NVALS][NWARPS];
    const int lane = threadIdx.x & 31;
    const int warp = threadIdx.x >> 5;

    #pragma unroll
    for (int c = 0; c < NUM_CLASSES; c++) {
        float v = warp_sum(acc_int[c]);
        if (lane == 0) s_part[c][warp] = v;
    }
    #pragma unroll
    for (int c = 0; c < NUM_CLASSES; c++) {
        float v = warp_sum(acc_den[c]);
        if (lane == 0) s_part[NUM_CLASSES + c][warp] = v;
    }
    {
        float v = warp_sum(acc_ce);
        if (lane == 0) s_part[2 * NUM_CLASSES][warp] = v;
    }
    __syncthreads();

    // First NVALS threads finish the per-block sum in fixed order.
    if (threadIdx.x < NVALS) {
        float v = 0.f;
        #pragma unroll
        for (int w = 0; w < NWARPS; w++) v += s_part[threadIdx.x][w];
        g_scratch[threadIdx.x * GRID + blockIdx.x] = v;
    }
}

__global__ void combined_loss_pass2(float* __restrict__ out)
{
    __shared__ float finals[NVALS];
    const int tid  = threadIdx.x;
    const int warp = tid >> 5;
    const int lane = tid & 31;

    // 8 warps cover 47 values; lanes stride over the GRID blocks.
    for (int v = warp; v < NVALS; v += NWARPS) {
        float s = 0.f;
        for (int b = lane; b < GRID; b += 32)
            s += g_scratch[v * GRID + b];
        s = warp_sum(s);
        if (lane == 0) finals[v] = s;
    }
    __syncthreads();

    if (tid == 0) {
        float dl = 0.f;
        #pragma unroll
        for (int c = 0; c < NUM_CLASSES; c++) {
            const float inter = finals[c];
            const float den   = finals[NUM_CLASSES + c];
            const float dice  = (2.0f * inter + SMOOTH) / (den + SMOOTH);
            dl += 1.0f - dice;
        }
        dl *= (1.0f / NUM_CLASSES);
        const float ce = finals[2 * NUM_CLASSES] * (1.0f / (float)NPIX);
        out[0] = 0.5f * dl + 0.5f * ce;
    }
}

extern "C" void kernel_launch(void* const* d_in, const int* in_sizes, int n_in,
                              void* d_out, int out_size)
{
    const float* pred = (const float*)d_in[0];
    const int*   tgt  = (const int*)d_in[1];
    float*       out  = (float*)d_out;
    (void)in_sizes; (void)n_in; (void)out_size;

    combined_loss_pass1<<<GRID, BLOCK>>>(pred, tgt);
    combined_loss_pass2<<<1, BLOCK>>>(out);
}

// round 3
// speedup vs baseline: 1.1185x; 1.1185x over previous
#include <cuda_runtime.h>

#define NUM_CLASSES 23
#define HW (512*512)               // 262144 = 2^18
#define HW_SHIFT 18
#define NPIX (8*HW)                // 2097152
#define NPAIR (NPIX/2)             // 1048576
#define GRID 296
#define BLOCK 256
#define NWARPS (BLOCK/32)
#define NVALS (2*NUM_CLASSES + 1)  // 47
#define SMOOTH 1e-5f

__device__ float g_scratch[NVALS * GRID];
__device__ unsigned int g_count;   // zero-initialized; self-resetting each launch

__device__ __forceinline__ float warp_sum(float v) {
    #pragma unroll
    for (int off = 16; off; off >>= 1)
        v += __shfl_down_sync(0xffffffffu, v, off);
    return v;
}

__global__ __launch_bounds__(BLOCK, 2)
void combined_loss_fused(const float* __restrict__ pred,
                         const int*  __restrict__ tgt,
                         float* __restrict__ out)
{
    float acc_int[NUM_CLASSES];
    float acc_den[NUM_CLASSES];
    #pragma unroll
    for (int c = 0; c < NUM_CLASSES; c++) { acc_int[c] = 0.f; acc_den[c] = 0.f; }
    float acc_ce = 0.f;

    const int tid0   = blockIdx.x * BLOCK + threadIdx.x;
    const int stride = GRID * BLOCK;

    for (int q = tid0; q < NPAIR; q += stride) {
        const int p  = q << 1;                       // first pixel of the pair
        const int b  = p >> HW_SHIFT;
        const int hw = p & (HW - 1);                 // even -> 8B aligned
        const float* base = pred + (size_t)b * (NUM_CLASSES * HW) + hw;
        const int2 t2 = ((const int2*)tgt)[q];

        // Pass A: vector loads, running max per element
        float2 x[NUM_CLASSES];
        float m0 = -1e30f, m1 = -1e30f;
        #pragma unroll
        for (int c = 0; c < NUM_CLASSES; c++) {
            x[c] = *(const float2*)(base + c * HW);
            m0 = fmaxf(m0, x[c].x);
            m1 = fmaxf(m1, x[c].y);
        }
        float xt0 = 0.f, xt1 = 0.f;
        #pragma unroll
        for (int c = 0; c < NUM_CLASSES; c++) {
            xt0 = (c == t2.x) ? x[c].x : xt0;
            xt1 = (c == t2.y) ? x[c].y : xt1;
        }

        // Pass B: exp + sum
        float s0 = 0.f, s1 = 0.f;
        #pragma unroll
        for (int c = 0; c < NUM_CLASSES; c++) {
            x[c].x = __expf(x[c].x - m0);
            x[c].y = __expf(x[c].y - m1);
            s0 += x[c].x;
            s1 += x[c].y;
        }
        const float inv0 = 1.0f / s0;
        const float inv1 = 1.0f / s1;

        // Pass C: per-class dice stats (predicated register scatter)
        #pragma unroll
        for (int c = 0; c < NUM_CLASSES; c++) {
            const float pr0 = x[c].x * inv0;
            const float pr1 = x[c].y * inv1;
            const bool h0 = (c == t2.x);
            const bool h1 = (c == t2.y);
            acc_den[c] += pr0 + pr1 + (h0 ? 1.0f : 0.0f) + (h1 ? 1.0f : 0.0f);
            acc_int[c] += (h0 ? pr0 : 0.0f) + (h1 ? pr1 : 0.0f);
        }

        acc_ce += (m0 + __logf(s0)) - xt0;
        acc_ce += (m1 + __logf(s1)) - xt1;
    }

    // Block reduction: warp shfl -> shared -> serial over warps (fixed order)
    __shared__ float s_part[NVALS][NWARPS];
    const int lane = threadIdx.x & 31;
    const int warp = threadIdx.x >> 5;

    #pragma unroll
    for (int c = 0; c < NUM_CLASSES; c++) {
        float v = warp_sum(acc_int[c]);
        if (lane == 0) s_part[c][warp] = v;
    }
    #pragma unroll
    for (int c = 0; c < NUM_CLASSES; c++) {
        float v = warp_sum(acc_den[c]);
        if (lane == 0) s_part[NUM_CLASSES + c][warp] = v;
    }
    {
        float v = warp_sum(acc_ce);
        if (lane == 0) s_part[2 * NUM_CLASSES][warp] = v;
    }
    __syncthreads();

    if (threadIdx.x < NVALS) {
        float v = 0.f;
        #pragma unroll
        for (int w = 0; w < NWARPS; w++) v += s_part[threadIdx.x][w];
        g_scratch[threadIdx.x * GRID + blockIdx.x] = v;
    }

    // Last-block final reduction (deterministic: fixed block-index order)
    __shared__ bool is_last;
    __threadfence();                       // publish partials
    if (threadIdx.x == 0) {
        unsigned int v = atomicAdd(&g_count, 1u);
        is_last = (v == GRID - 1);
        if (is_last) g_count = 0u;         // reset for next graph replay
    }
    __syncthreads();
    if (!is_last) return;

    __shared__ float finals[NVALS];
    for (int v = warp; v < NVALS; v += NWARPS) {
        float s = 0.f;
        for (int bk = lane; bk < GRID; bk += 32)
            s += __ldcg(&g_scratch[v * GRID + bk]);   // bypass L1 (other blocks wrote)
        s = warp_sum(s);
        if (lane == 0) finals[v] = s;
    }
    __syncthreads();

    if (threadIdx.x == 0) {
        float dl = 0.f;
        #pragma unroll
        for (int c = 0; c < NUM_CLASSES; c++) {
            const float inter = finals[c];
            const float den   = finals[NUM_CLASSES + c];
            dl += 1.0f - (2.0f * inter + SMOOTH) / (den + SMOOTH);
        }
        dl *= (1.0f / NUM_CLASSES);
        const float ce = finals[2 * NUM_CLASSES] * (1.0f / (float)NPIX);
        out[0] = 0.5f * dl + 0.5f * ce;
    }
}

extern "C" void kernel_launch(void* const* d_in, const int* in_sizes, int n_in,
                              void* d_out, int out_size)
{
    const float* pred = (const float*)d_in[0];
    const int*   tgt  = (const int*)d_in[1];
    float*       out  = (float*)d_out;
    (void)in_sizes; (void)n_in; (void)out_size;

    combined_loss_fused<<<GRID, BLOCK>>>(pred, tgt, out);
}